// round 5
// baseline (speedup 1.0000x reference)
#include <cuda_runtime.h>
#include <cstdint>

#define NN 50000
#define NE 312500
#define NG 50
#define DIN 384
#define DH 256
#define DOUT 256

// ---- scratch (allocation-free: __device__ globals) ----
__device__ float g_h[(size_t)NN * DH];     // node features
__device__ float g_e[(size_t)NE * DH];     // projected edge features
__device__ float g_aggr[(size_t)NN * DH];  // z accumulator: (1+eps)h + scatter-sum
__device__ float g_t[(size_t)NN * DH];     // relu(z@W1+b1)
__device__ float g_pool[NG * DH];
__device__ float g_cnt[NG];
__device__ int   g_root[NG];
__device__ int   g_src[NE];
__device__ int   g_dst[NE];
__device__ int   g_batch[NN];
__device__ int   g_is64;                   // 1 if index buffers are int64

// ============================================================
// dtype detection: scan odd 32-bit words of first 2*NE words of
// edge_index. int64 (values < 2^31): all high words == 0.
// int32: words are random indices in [0,NN) -> some nonzero.
// Single block, deterministic, overwrites g_is64 (no pre-zero needed).
// ============================================================
__global__ __launch_bounds__(1024) void detect_kernel(const unsigned* __restrict__ w)
{
    __shared__ unsigned red[32];
    unsigned acc = 0;
    for (int i = threadIdx.x; i < NE; i += 1024)
        acc |= w[2 * i + 1];
#pragma unroll
    for (int o = 16; o > 0; o >>= 1) acc |= __shfl_xor_sync(0xffffffffu, acc, o);
    if ((threadIdx.x & 31) == 0) red[threadIdx.x >> 5] = acc;
    __syncthreads();
    if (threadIdx.x < 32) {
        unsigned v = red[threadIdx.x];
#pragma unroll
        for (int o = 16; o > 0; o >>= 1) v |= __shfl_xor_sync(0xffffffffu, v, o);
        if (threadIdx.x == 0) g_is64 = (v == 0u) ? 1 : 0;
    }
}

// convert edge_index -> src/dst int32, batch -> int32 (clamped)
__global__ void convert_idx_kernel(const void* __restrict__ ei, const void* __restrict__ batch)
{
    int i = blockIdx.x * blockDim.x + threadIdx.x;
    const int is64 = g_is64;
    if (i < NE) {
        long long s, d;
        if (is64) {
            s = ((const long long*)ei)[i];
            d = ((const long long*)ei)[NE + i];
        } else {
            s = ((const int*)ei)[i];
            d = ((const int*)ei)[NE + i];
        }
        g_src[i] = (int)min((long long)(NN - 1), max(0LL, s));
        g_dst[i] = (int)min((long long)(NN - 1), max(0LL, d));
    }
    if (i < NN) {
        long long b = is64 ? ((const long long*)batch)[i] : (long long)((const int*)batch)[i];
        g_batch[i] = (int)min((long long)(NG - 1), max(0LL, b));
    }
}

// ============================================================
// SGEMM: C[M,256] = epilogue(A[M,K] @ W[K,256] + bias)
//   MODE 0: C = AB + b
//   MODE 1: C = relu(AB + b)
//   MODE 2: C = relu(AB + b + res)   (res may alias C; 1 writer/elem)
// Tiles: BM=128, BN=128, BK=16, 256 threads, 8x8 per-thread microtile.
// Double-buffered smem with register prefetch of the next K-tile.
// ============================================================
template <int MODE>
__global__ __launch_bounds__(256) void sgemm_kernel(
    const float* __restrict__ A, const float* __restrict__ W,
    const float* __restrict__ bias, float* C,
    const float* res, int M, int K)
{
    constexpr int BK = 16;
    __shared__ __align__(16) float As[2][BK][132];  // transposed, padded
    __shared__ __align__(16) float Bs[2][BK][128];

    const int t  = threadIdx.x;
    const int m0 = blockIdx.x * 128;
    const int n0 = blockIdx.y * 128;
    const int tx = t & 15;      // 16 cols of threads * 8 = 128
    const int ty = t >> 4;      // 16 rows of threads * 8 = 128

    const int a_row0 = (t + 0)   >> 2, a_kc0 = (t + 0)   & 3;
    const int a_row1 = (t + 256) >> 2, a_kc1 = (t + 256) & 3;
    const int b_row0 = (t + 0)   >> 5, b_col0 = (t + 0)   & 31;
    const int b_row1 = (t + 256) >> 5, b_col1 = (t + 256) & 31;

    float4 ra0, ra1, rb0, rb1;

    auto load_regs = [&](int k0) {
        ra0 = make_float4(0.f, 0.f, 0.f, 0.f);
        ra1 = make_float4(0.f, 0.f, 0.f, 0.f);
        int gm0 = m0 + a_row0, gm1 = m0 + a_row1;
        if (gm0 < M) ra0 = *reinterpret_cast<const float4*>(&A[(size_t)gm0 * K + k0 + a_kc0 * 4]);
        if (gm1 < M) ra1 = *reinterpret_cast<const float4*>(&A[(size_t)gm1 * K + k0 + a_kc1 * 4]);
        rb0 = *reinterpret_cast<const float4*>(&W[(size_t)(k0 + b_row0) * 256 + n0 + b_col0 * 4]);
        rb1 = *reinterpret_cast<const float4*>(&W[(size_t)(k0 + b_row1) * 256 + n0 + b_col1 * 4]);
    };
    auto store_smem = [&](int buf) {
        As[buf][a_kc0 * 4 + 0][a_row0] = ra0.x;
        As[buf][a_kc0 * 4 + 1][a_row0] = ra0.y;
        As[buf][a_kc0 * 4 + 2][a_row0] = ra0.z;
        As[buf][a_kc0 * 4 + 3][a_row0] = ra0.w;
        As[buf][a_kc1 * 4 + 0][a_row1] = ra1.x;
        As[buf][a_kc1 * 4 + 1][a_row1] = ra1.y;
        As[buf][a_kc1 * 4 + 2][a_row1] = ra1.z;
        As[buf][a_kc1 * 4 + 3][a_row1] = ra1.w;
        *reinterpret_cast<float4*>(&Bs[buf][b_row0][b_col0 * 4]) = rb0;
        *reinterpret_cast<float4*>(&Bs[buf][b_row1][b_col1 * 4]) = rb1;
    };

    float acc[8][8];
#pragma unroll
    for (int i = 0; i < 8; i++)
#pragma unroll
        for (int j = 0; j < 8; j++) acc[i][j] = 0.f;

    load_regs(0);
    store_smem(0);
    __syncthreads();

    int buf = 0;
    for (int k0 = 0; k0 < K; k0 += BK) {
        const bool has_next = (k0 + BK) < K;
        if (has_next) load_regs(k0 + BK);   // overlap with compute below

#pragma unroll
        for (int kk = 0; kk < BK; kk++) {
            float4 a0 = *reinterpret_cast<const float4*>(&As[buf][kk][ty * 8]);
            float4 a1 = *reinterpret_cast<const float4*>(&As[buf][kk][ty * 8 + 4]);
            float4 b0 = *reinterpret_cast<const float4*>(&Bs[buf][kk][tx * 8]);
            float4 b1 = *reinterpret_cast<const float4*>(&Bs[buf][kk][tx * 8 + 4]);
            float av[8] = {a0.x, a0.y, a0.z, a0.w, a1.x, a1.y, a1.z, a1.w};
            float bv[8] = {b0.x, b0.y, b0.z, b0.w, b1.x, b1.y, b1.z, b1.w};
#pragma unroll
            for (int i = 0; i < 8; i++)
#pragma unroll
                for (int j = 0; j < 8; j++)
                    acc[i][j] = fmaf(av[i], bv[j], acc[i][j]);
        }

        if (has_next) {
            store_smem(buf ^ 1);
            buf ^= 1;
            __syncthreads();
        }
    }

    float bb[8];
#pragma unroll
    for (int j = 0; j < 8; j++) bb[j] = bias[n0 + tx * 8 + j];

#pragma unroll
    for (int i = 0; i < 8; i++) {
        int gm = m0 + ty * 8 + i;
        if (gm < M) {
            size_t base = (size_t)gm * 256 + n0 + tx * 8;
#pragma unroll
            for (int jv = 0; jv < 2; jv++) {
                float v[4];
#pragma unroll
                for (int j = 0; j < 4; j++) {
                    float x = acc[i][jv * 4 + j] + bb[jv * 4 + j];
                    if (MODE == 2) x += res[base + jv * 4 + j];
                    if (MODE >= 1) x = fmaxf(x, 0.f);
                    v[j] = x;
                }
                *reinterpret_cast<float4*>(&C[base + jv * 4]) =
                    make_float4(v[0], v[1], v[2], v[3]);
            }
        }
    }
}

// ============================================================
// message + scatter: aggr[dst] += relu(h[src] + e), warp per edge
// ============================================================
__global__ __launch_bounds__(256) void message_kernel(
    const float* __restrict__ h, const float* __restrict__ e,
    float* __restrict__ aggr)
{
    int warp = (blockIdx.x * blockDim.x + threadIdx.x) >> 5;
    int lane = threadIdx.x & 31;
    if (warp >= NE) return;
    int s = g_src[warp];
    int d = g_dst[warp];
    const float4* hs = reinterpret_cast<const float4*>(h + (size_t)s * DH);
    const float4* es = reinterpret_cast<const float4*>(e + (size_t)warp * DH);
    float* ad = aggr + (size_t)d * DH;
#pragma unroll
    for (int i = 0; i < 2; i++) {
        int f = lane + i * 32;  // float4 index 0..63
        float4 hv = hs[f];
        float4 ev = es[f];
        float mx = fmaxf(hv.x + ev.x, 0.f);
        float my = fmaxf(hv.y + ev.y, 0.f);
        float mz = fmaxf(hv.z + ev.z, 0.f);
        float mw = fmaxf(hv.w + ev.w, 0.f);
        asm volatile("red.global.add.v4.f32 [%0], {%1,%2,%3,%4};"
                     :: "l"(ad + (size_t)f * 4), "f"(mx), "f"(my), "f"(mz), "f"(mw)
                     : "memory");
    }
}

// ---- init z accumulator: aggr = (1+eps)*h  (scatter adds land on top) ----
__global__ void init_z_kernel(const float* __restrict__ h, const float* __restrict__ eps,
                              float* __restrict__ aggr)
{
    size_t i = (size_t)blockIdx.x * blockDim.x + threadIdx.x;
    size_t n = (size_t)NN * DH / 4;
    if (i >= n) return;
    float s = 1.0f + *eps;
    float4 hv = reinterpret_cast<const float4*>(h)[i];
    reinterpret_cast<float4*>(aggr)[i] =
        make_float4(s * hv.x, s * hv.y, s * hv.z, s * hv.w);
}

__global__ void zero_kernel(float* __restrict__ p, int n)
{
    int i = blockIdx.x * blockDim.x + threadIdx.x;
    if (i < n) p[i] = 0.f;
}

// ---- pooling: batch is sorted; run-length accumulate, few atomics ----
__global__ __launch_bounds__(256) void pool_kernel(
    const float* __restrict__ h, float* __restrict__ pool, float* __restrict__ cnt)
{
    const int f = threadIdx.x;           // feature 0..255
    int start = blockIdx.x * 100;
    int end = start + 100;
    if (end > NN) end = NN;
    if (start >= NN) return;
    float acc = 0.f;
    int cur = g_batch[start];
    int runlen = 0;
    for (int i = start; i < end; i++) {
        int b = g_batch[i];
        if (b != cur) {
            atomicAdd(&pool[cur * DH + f], acc);
            if (f == 0) atomicAdd(&cnt[cur], (float)runlen);
            acc = 0.f; runlen = 0; cur = b;
        }
        acc += h[(size_t)i * DH + f];
        runlen++;
    }
    atomicAdd(&pool[cur * DH + f], acc);
    if (f == 0) atomicAdd(&cnt[cur], (float)runlen);
}

__global__ void root_kernel(int* __restrict__ root)
{
    int i = blockIdx.x * blockDim.x + threadIdx.x;
    if (i >= NN) return;
    int b = g_batch[i];
    if (i == 0 || g_batch[i - 1] != b) root[b] = i;
}

// ---- out[g] = (pool[g]/cnt[g] + alpha*h[root[g]]) @ Wo + bo ----
__global__ __launch_bounds__(256) void final_kernel(
    const float* __restrict__ h, const float* __restrict__ pool,
    const float* __restrict__ cnt, const int* __restrict__ root,
    const float* __restrict__ Wo, const float* __restrict__ bo,
    const float* __restrict__ alpha, float* __restrict__ out)
{
    __shared__ float vec[DH];
    int g = blockIdx.x;
    int t = threadIdx.x;
    float a = *alpha;
    vec[t] = pool[g * DH + t] / cnt[g] + a * h[(size_t)root[g] * DH + t];
    __syncthreads();
    float s = bo[t];
#pragma unroll 8
    for (int k = 0; k < DH; k++) s = fmaf(vec[k], Wo[k * DOUT + t], s);
    out[g * DOUT + t] = s;
}

// ============================================================
extern "C" void kernel_launch(void* const* d_in, const int* in_sizes, int n_in,
                              void* d_out, int out_size)
{
    const float* x    = (const float*)d_in[0];
    const float* ea   = (const float*)d_in[1];
    const float* Wn   = (const float*)d_in[2];
    const float* bn   = (const float*)d_in[3];
    const float* We   = (const float*)d_in[4];
    const float* be   = (const float*)d_in[5];
    const float* c1W1 = (const float*)d_in[6];
    const float* c1b1 = (const float*)d_in[7];
    const float* c1W2 = (const float*)d_in[8];
    const float* c1b2 = (const float*)d_in[9];
    const float* eps1 = (const float*)d_in[10];
    const float* c2W1 = (const float*)d_in[11];
    const float* c2b1 = (const float*)d_in[12];
    const float* c2W2 = (const float*)d_in[13];
    const float* c2b2 = (const float*)d_in[14];
    const float* eps2 = (const float*)d_in[15];
    const float* Wo   = (const float*)d_in[16];
    const float* bo   = (const float*)d_in[17];
    const float* alpha= (const float*)d_in[18];
    const void*  ei    = d_in[19];
    const void*  batch = d_in[20];
    float* out = (float*)d_out;

    float *ph, *pe, *pa, *pt, *ppool, *pcnt;
    int* proot;
    cudaGetSymbolAddress((void**)&ph, g_h);
    cudaGetSymbolAddress((void**)&pe, g_e);
    cudaGetSymbolAddress((void**)&pa, g_aggr);
    cudaGetSymbolAddress((void**)&pt, g_t);
    cudaGetSymbolAddress((void**)&ppool, g_pool);
    cudaGetSymbolAddress((void**)&pcnt, g_cnt);
    cudaGetSymbolAddress((void**)&proot, g_root);

    const dim3 gridN((NN + 127) / 128, 2);
    const dim3 gridE((NE + 127) / 128, 2);
    const size_t nh4 = (size_t)NN * DH / 4;
    const int zblocks = (int)((nh4 + 255) / 256);

    // index dtype detection + conversion to int32
    detect_kernel<<<1, 1024>>>((const unsigned*)ei);
    convert_idx_kernel<<<(NE + 255) / 256, 256>>>(ei, batch);

    // projections
    sgemm_kernel<0><<<gridN, 256>>>(x,  Wn, bn, ph, nullptr, NN, DIN);
    sgemm_kernel<0><<<gridE, 256>>>(ea, We, be, pe, nullptr, NE, DIN);

    // two GINE layers
    for (int layer = 0; layer < 2; layer++) {
        const float* W1 = layer ? c2W1 : c1W1;
        const float* b1 = layer ? c2b1 : c1b1;
        const float* W2 = layer ? c2W2 : c1W2;
        const float* b2 = layer ? c2b2 : c1b2;
        const float* ep = layer ? eps2 : eps1;

        init_z_kernel<<<zblocks, 256>>>(ph, ep, pa);            // aggr = (1+eps)*h
        message_kernel<<<(NE * 32 + 255) / 256, 256>>>(ph, pe, pa);
        sgemm_kernel<1><<<gridN, 256>>>(pa, W1, b1, pt, nullptr, NN, DH);
        sgemm_kernel<2><<<gridN, 256>>>(pt, W2, b2, ph, ph, NN, DH);
    }

    // pooling + head
    zero_kernel<<<(NG * DH + 255) / 256, 256>>>(ppool, NG * DH);
    zero_kernel<<<1, 64>>>(pcnt, NG);
    pool_kernel<<<(NN + 99) / 100, 256>>>(ph, ppool, pcnt);
    root_kernel<<<(NN + 255) / 256, 256>>>(proot);
    final_kernel<<<NG, 256>>>(ph, ppool, pcnt, proot, Wo, bo, alpha, out);
}

// round 7
// speedup vs baseline: 2.0806x; 2.0806x over previous
#include <cuda_runtime.h>
#include <cuda_bf16.h>
#include <cstdint>

#define NN 50000
#define NE 312500
#define NG 50
#define DIN 384
#define DH 256
#define DOUT 256

// ---- scratch (allocation-free: __device__ globals) ----
__device__ float g_h[(size_t)NN * DH];
__device__ float g_e[(size_t)NE * DH];
__device__ float g_aggr[(size_t)NN * DH];
__device__ float g_t[(size_t)NN * DH];
__device__ float g_pool[NG * DH];
__device__ float g_cnt[NG];
__device__ int   g_root[NG];
__device__ int   g_src[NE];
__device__ int   g_dst[NE];
__device__ int   g_batch[NN];
__device__ int   g_is64;

// transposed + hi/lo-split weights: [N=256, K] bf16, K-major rows
// offsets (elems): Wn:0  We:98304  c1W1:196608  c1W2:262144  c2W1:327680  c2W2:393216
#define WT_TOTAL 458752
__device__ __nv_bfloat16 g_whi[WT_TOTAL];
__device__ __nv_bfloat16 g_wlo[WT_TOTAL];

// ============================================================
// baseline-PTX tensor helpers (sm_80 features; OK at compute_103)
// ============================================================
__device__ __forceinline__ void ldsm_x4(uint32_t& r0, uint32_t& r1, uint32_t& r2, uint32_t& r3,
                                        uint32_t addr) {
    asm volatile("ldmatrix.sync.aligned.m8n8.x4.shared.b16 {%0,%1,%2,%3}, [%4];"
                 : "=r"(r0), "=r"(r1), "=r"(r2), "=r"(r3) : "r"(addr));
}
__device__ __forceinline__ void mma16816(float* c, const uint32_t* a, const uint32_t* b) {
    asm volatile(
        "mma.sync.aligned.m16n8k16.row.col.f32.bf16.bf16.f32 "
        "{%0,%1,%2,%3}, {%4,%5,%6,%7}, {%8,%9}, {%0,%1,%2,%3};"
        : "+f"(c[0]), "+f"(c[1]), "+f"(c[2]), "+f"(c[3])
        : "r"(a[0]), "r"(a[1]), "r"(a[2]), "r"(a[3]), "r"(b[0]), "r"(b[1]));
}
__device__ __forceinline__ void split2(float a, float b, uint32_t& hi, uint32_t& lo) {
    __nv_bfloat16 ha = __float2bfloat16(a), hb = __float2bfloat16(b);
    float ra = a - __bfloat162float(ha);
    float rb = b - __bfloat162float(hb);
    hi = (uint32_t)__bfloat16_as_ushort(ha) | ((uint32_t)__bfloat16_as_ushort(hb) << 16);
    lo = (uint32_t)__bfloat16_as_ushort(__float2bfloat16(ra)) |
         ((uint32_t)__bfloat16_as_ushort(__float2bfloat16(rb)) << 16);
}

// ============================================================
// dtype detection for int64-vs-int32 index buffers
// ============================================================
__global__ __launch_bounds__(1024) void detect_kernel(const unsigned* __restrict__ w)
{
    __shared__ unsigned red[32];
    unsigned acc = 0;
    for (int i = threadIdx.x; i < NE; i += 1024)
        acc |= w[2 * i + 1];
#pragma unroll
    for (int o = 16; o > 0; o >>= 1) acc |= __shfl_xor_sync(0xffffffffu, acc, o);
    if ((threadIdx.x & 31) == 0) red[threadIdx.x >> 5] = acc;
    __syncthreads();
    if (threadIdx.x < 32) {
        unsigned v = red[threadIdx.x];
#pragma unroll
        for (int o = 16; o > 0; o >>= 1) v |= __shfl_xor_sync(0xffffffffu, v, o);
        if (threadIdx.x == 0) g_is64 = (v == 0u) ? 1 : 0;
    }
}

__global__ void convert_idx_kernel(const void* __restrict__ ei, const void* __restrict__ batch)
{
    int i = blockIdx.x * blockDim.x + threadIdx.x;
    const int is64 = g_is64;
    if (i < NE) {
        long long s, d;
        if (is64) {
            s = ((const long long*)ei)[i];
            d = ((const long long*)ei)[NE + i];
        } else {
            s = ((const int*)ei)[i];
            d = ((const int*)ei)[NE + i];
        }
        g_src[i] = (int)min((long long)(NN - 1), max(0LL, s));
        g_dst[i] = (int)min((long long)(NN - 1), max(0LL, d));
    }
    if (i < NN) {
        long long b = is64 ? ((const long long*)batch)[i] : (long long)((const int*)batch)[i];
        g_batch[i] = (int)min((long long)(NG - 1), max(0LL, b));
    }
}

// ---- weight prep: W[K,256] fp32 -> Wt hi/lo [256,K] bf16 ----
__global__ void prep_w_kernel(const float* __restrict__ W, int K, int off)
{
    int idx = blockIdx.x * blockDim.x + threadIdx.x;
    if (idx >= K * 256) return;
    int k = idx >> 8, n = idx & 255;
    float w = W[idx];
    __nv_bfloat16 h = __float2bfloat16(w);
    float r = w - __bfloat162float(h);
    g_whi[off + n * K + k] = h;
    g_wlo[off + n * K + k] = __float2bfloat16(r);
}

// ============================================================
// bf16x2-split mma.sync GEMM: C[M,256] = epi(A[M,K] @ W[K,256] + bias)
// C ≈ Ahi·Bhi + Ahi·Blo + Alo·Bhi  (fp32 accum)
// CTA 128x128, 256 threads, 8 warps (2x4), warp tile 64x32, BK=32.
// smem rows padded to 40 elems (80B) -> conflict-free ldmatrix.
// MODE 0: C=AB+b ; 1: relu ; 2: relu(AB+b+res) (res may alias C)
// ============================================================
template <int MODE>
__global__ __launch_bounds__(256) void tgemm_kernel(
    const float* __restrict__ A,
    const __nv_bfloat16* __restrict__ Bh, const __nv_bfloat16* __restrict__ Bl,
    const float* __restrict__ bias, float* C, const float* res, int M, int K)
{
    __shared__ __nv_bfloat16 sAh[128][40];
    __shared__ __nv_bfloat16 sAl[128][40];
    __shared__ __nv_bfloat16 sBh[128][40];
    __shared__ __nv_bfloat16 sBl[128][40];

    const int tid = threadIdx.x;
    const int lane = tid & 31, wid = tid >> 5;
    const int warp_m = wid >> 2, warp_n = wid & 3;   // 2 x 4 warp grid
    const int m0 = blockIdx.x * 128, n0 = blockIdx.y * 128;

    // loader coords: thread -> (row, k-half)
    const int lm  = tid >> 1;
    const int lkh = (tid & 1) * 16;

    // ldmatrix per-lane element coords
    const int a_r = lane & 15;
    const int a_c = (lane >> 4) << 3;
    const int b_r = ((lane >> 4) << 3) + (lane & 7);
    const int b_c = ((lane >> 3) & 1) << 3;

    const uint32_t uAh = (uint32_t)__cvta_generic_to_shared(&sAh[0][0]);
    const uint32_t uAl = (uint32_t)__cvta_generic_to_shared(&sAl[0][0]);
    const uint32_t uBh = (uint32_t)__cvta_generic_to_shared(&sBh[0][0]);
    const uint32_t uBl = (uint32_t)__cvta_generic_to_shared(&sBl[0][0]);

    float acc[4][4][4];
#pragma unroll
    for (int i = 0; i < 4; i++)
#pragma unroll
        for (int j = 0; j < 4; j++)
#pragma unroll
            for (int q = 0; q < 4; q++) acc[i][j][q] = 0.f;

    for (int k0 = 0; k0 < K; k0 += 32) {
        // ---- load + split A: 16 fp32 per thread ----
        {
            const int gm = m0 + lm;
            uint32_t hh[8], ll[8];
            if (gm < M) {
                const float* ap = A + (size_t)gm * K + k0 + lkh;
#pragma unroll
                for (int j = 0; j < 4; j++) {
                    float4 v = *reinterpret_cast<const float4*>(ap + j * 4);
                    split2(v.x, v.y, hh[2 * j],     ll[2 * j]);
                    split2(v.z, v.w, hh[2 * j + 1], ll[2 * j + 1]);
                }
            } else {
#pragma unroll
                for (int j = 0; j < 8; j++) { hh[j] = 0u; ll[j] = 0u; }
            }
            uint32_t* dh = reinterpret_cast<uint32_t*>(&sAh[lm][lkh]);
            uint32_t* dl = reinterpret_cast<uint32_t*>(&sAl[lm][lkh]);
            *reinterpret_cast<uint4*>(dh)     = make_uint4(hh[0], hh[1], hh[2], hh[3]);
            *reinterpret_cast<uint4*>(dh + 4) = make_uint4(hh[4], hh[5], hh[6], hh[7]);
            *reinterpret_cast<uint4*>(dl)     = make_uint4(ll[0], ll[1], ll[2], ll[3]);
            *reinterpret_cast<uint4*>(dl + 4) = make_uint4(ll[4], ll[5], ll[6], ll[7]);
        }
        // ---- load B hi/lo: 16 bf16 per thread each ----
        {
            const size_t go = (size_t)(n0 + lm) * K + k0 + lkh;
            uint4 v0 = *reinterpret_cast<const uint4*>(Bh + go);
            uint4 v1 = *reinterpret_cast<const uint4*>(Bh + go + 8);
            uint4 w0 = *reinterpret_cast<const uint4*>(Bl + go);
            uint4 w1 = *reinterpret_cast<const uint4*>(Bl + go + 8);
            *reinterpret_cast<uint4*>(&sBh[lm][lkh])     = v0;
            *reinterpret_cast<uint4*>(&sBh[lm][lkh + 8]) = v1;
            *reinterpret_cast<uint4*>(&sBl[lm][lkh])     = w0;
            *reinterpret_cast<uint4*>(&sBl[lm][lkh + 8]) = w1;
        }
        __syncthreads();

#pragma unroll
        for (int ks = 0; ks < 2; ks++) {
            uint32_t ah[4][4], al[4][4], bh[4][2], bl[4][2];
#pragma unroll
            for (int mt = 0; mt < 4; mt++) {
                int r = warp_m * 64 + mt * 16 + a_r;
                int c = ks * 16 + a_c;
                uint32_t off = (uint32_t)(r * 40 + c) * 2;
                ldsm_x4(ah[mt][0], ah[mt][1], ah[mt][2], ah[mt][3], uAh + off);
                ldsm_x4(al[mt][0], al[mt][1], al[mt][2], al[mt][3], uAl + off);
            }
#pragma unroll
            for (int np = 0; np < 2; np++) {
                int r = warp_n * 32 + np * 16 + b_r;
                int c = ks * 16 + b_c;
                uint32_t off = (uint32_t)(r * 40 + c) * 2;
                uint32_t r0, r1, r2, r3;
                ldsm_x4(r0, r1, r2, r3, uBh + off);
                bh[2 * np][0] = r0; bh[2 * np][1] = r1;
                bh[2 * np + 1][0] = r2; bh[2 * np + 1][1] = r3;
                ldsm_x4(r0, r1, r2, r3, uBl + off);
                bl[2 * np][0] = r0; bl[2 * np][1] = r1;
                bl[2 * np + 1][0] = r2; bl[2 * np + 1][1] = r3;
            }
#pragma unroll
            for (int mt = 0; mt < 4; mt++)
#pragma unroll
                for (int nt = 0; nt < 4; nt++) {
                    mma16816(acc[mt][nt], ah[mt], bh[nt]);
                    mma16816(acc[mt][nt], ah[mt], bl[nt]);
                    mma16816(acc[mt][nt], al[mt], bh[nt]);
                }
        }
        __syncthreads();
    }

    // ---- epilogue ----
#pragma unroll
    for (int nt = 0; nt < 4; nt++) {
        const int gn = n0 + warp_n * 32 + nt * 8 + (lane & 3) * 2;
        const float b0 = bias[gn], b1 = bias[gn + 1];
#pragma unroll
        for (int mt = 0; mt < 4; mt++) {
            const int gm = m0 + warp_m * 64 + mt * 16 + (lane >> 2);
#pragma unroll
            for (int half = 0; half < 2; half++) {
                const int r = gm + half * 8;
                if (r < M) {
                    float x0 = acc[mt][nt][2 * half]     + b0;
                    float x1 = acc[mt][nt][2 * half + 1] + b1;
                    size_t base = (size_t)r * 256 + gn;
                    if (MODE == 2) { x0 += res[base]; x1 += res[base + 1]; }
                    if (MODE >= 1) { x0 = fmaxf(x0, 0.f); x1 = fmaxf(x1, 0.f); }
                    *reinterpret_cast<float2*>(&C[base]) = make_float2(x0, x1);
                }
            }
        }
    }
}

// ============================================================
// message + scatter: aggr[dst] += relu(h[src] + e), warp per edge
// ============================================================
__global__ __launch_bounds__(256) void message_kernel(
    const float* __restrict__ h, const float* __restrict__ e,
    float* __restrict__ aggr)
{
    int warp = (blockIdx.x * blockDim.x + threadIdx.x) >> 5;
    int lane = threadIdx.x & 31;
    if (warp >= NE) return;
    int s = g_src[warp];
    int d = g_dst[warp];
    const float4* hs = reinterpret_cast<const float4*>(h + (size_t)s * DH);
    const float4* es = reinterpret_cast<const float4*>(e + (size_t)warp * DH);
    float* ad = aggr + (size_t)d * DH;
#pragma unroll
    for (int i = 0; i < 2; i++) {
        int f = lane + i * 32;
        float4 hv = hs[f];
        float4 ev = es[f];
        float mx = fmaxf(hv.x + ev.x, 0.f);
        float my = fmaxf(hv.y + ev.y, 0.f);
        float mz = fmaxf(hv.z + ev.z, 0.f);
        float mw = fmaxf(hv.w + ev.w, 0.f);
        asm volatile("red.global.add.v4.f32 [%0], {%1,%2,%3,%4};"
                     :: "l"(ad + (size_t)f * 4), "f"(mx), "f"(my), "f"(mz), "f"(mw)
                     : "memory");
    }
}

__global__ void init_z_kernel(const float* __restrict__ h, const float* __restrict__ eps,
                              float* __restrict__ aggr)
{
    size_t i = (size_t)blockIdx.x * blockDim.x + threadIdx.x;
    size_t n = (size_t)NN * DH / 4;
    if (i >= n) return;
    float s = 1.0f + *eps;
    float4 hv = reinterpret_cast<const float4*>(h)[i];
    reinterpret_cast<float4*>(aggr)[i] =
        make_float4(s * hv.x, s * hv.y, s * hv.z, s * hv.w);
}

__global__ void zero_kernel(float* __restrict__ p, int n)
{
    int i = blockIdx.x * blockDim.x + threadIdx.x;
    if (i < n) p[i] = 0.f;
}

__global__ __launch_bounds__(256) void pool_kernel(
    const float* __restrict__ h, float* __restrict__ pool, float* __restrict__ cnt)
{
    const int f = threadIdx.x;
    int start = blockIdx.x * 100;
    int end = start + 100;
    if (end > NN) end = NN;
    if (start >= NN) return;
    float acc = 0.f;
    int cur = g_batch[start];
    int runlen = 0;
    for (int i = start; i < end; i++) {
        int b = g_batch[i];
        if (b != cur) {
            atomicAdd(&pool[cur * DH + f], acc);
            if (f == 0) atomicAdd(&cnt[cur], (float)runlen);
            acc = 0.f; runlen = 0; cur = b;
        }
        acc += h[(size_t)i * DH + f];
        runlen++;
    }
    atomicAdd(&pool[cur * DH + f], acc);
    if (f == 0) atomicAdd(&cnt[cur], (float)runlen);
}

__global__ void root_kernel(int* __restrict__ root)
{
    int i = blockIdx.x * blockDim.x + threadIdx.x;
    if (i >= NN) return;
    int b = g_batch[i];
    if (i == 0 || g_batch[i - 1] != b) root[b] = i;
}

__global__ __launch_bounds__(256) void final_kernel(
    const float* __restrict__ h, const float* __restrict__ pool,
    const float* __restrict__ cnt, const int* __restrict__ root,
    const float* __restrict__ Wo, const float* __restrict__ bo,
    const float* __restrict__ alpha, float* __restrict__ out)
{
    __shared__ float vec[DH];
    int g = blockIdx.x;
    int t = threadIdx.x;
    float a = *alpha;
    vec[t] = pool[g * DH + t] / cnt[g] + a * h[(size_t)root[g] * DH + t];
    __syncthreads();
    float s = bo[t];
#pragma unroll 8
    for (int k = 0; k < DH; k++) s = fmaf(vec[k], Wo[k * DOUT + t], s);
    out[g * DOUT + t] = s;
}

// ============================================================
extern "C" void kernel_launch(void* const* d_in, const int* in_sizes, int n_in,
                              void* d_out, int out_size)
{
    const float* x    = (const float*)d_in[0];
    const float* ea   = (const float*)d_in[1];
    const float* Wn   = (const float*)d_in[2];
    const float* bn   = (const float*)d_in[3];
    const float* We   = (const float*)d_in[4];
    const float* be   = (const float*)d_in[5];
    const float* c1W1 = (const float*)d_in[6];
    const float* c1b1 = (const float*)d_in[7];
    const float* c1W2 = (const float*)d_in[8];
    const float* c1b2 = (const float*)d_in[9];
    const float* eps1 = (const float*)d_in[10];
    const float* c2W1 = (const float*)d_in[11];
    const float* c2b1 = (const float*)d_in[12];
    const float* c2W2 = (const float*)d_in[13];
    const float* c2b2 = (const float*)d_in[14];
    const float* eps2 = (const float*)d_in[15];
    const float* Wo   = (const float*)d_in[16];
    const float* bo   = (const float*)d_in[17];
    const float* alpha= (const float*)d_in[18];
    const void*  ei    = d_in[19];
    const void*  batch = d_in[20];
    float* out = (float*)d_out;

    float *ph, *pe, *pa, *pt, *ppool, *pcnt;
    int* proot;
    __nv_bfloat16 *pwh, *pwl;
    cudaGetSymbolAddress((void**)&ph, g_h);
    cudaGetSymbolAddress((void**)&pe, g_e);
    cudaGetSymbolAddress((void**)&pa, g_aggr);
    cudaGetSymbolAddress((void**)&pt, g_t);
    cudaGetSymbolAddress((void**)&ppool, g_pool);
    cudaGetSymbolAddress((void**)&pcnt, g_cnt);
    cudaGetSymbolAddress((void**)&proot, g_root);
    cudaGetSymbolAddress((void**)&pwh, g_whi);
    cudaGetSymbolAddress((void**)&pwl, g_wlo);

    const dim3 gridN((NN + 127) / 128, 2);
    const dim3 gridE((NE + 127) / 128, 2);
    const size_t nh4 = (size_t)NN * DH / 4;
    const int zblocks = (int)((nh4 + 255) / 256);

    // index dtype detection + conversion
    detect_kernel<<<1, 1024>>>((const unsigned*)ei);
    convert_idx_kernel<<<(NE + 255) / 256, 256>>>(ei, batch);

    // weight prep: transpose + hi/lo split
    const int O_WN = 0, O_WE = 98304, O_11 = 196608, O_12 = 262144, O_21 = 327680, O_22 = 393216;
    prep_w_kernel<<<(DIN * 256 + 255) / 256, 256>>>(Wn,   DIN, O_WN);
    prep_w_kernel<<<(DIN * 256 + 255) / 256, 256>>>(We,   DIN, O_WE);
    prep_w_kernel<<<(DH  * 256 + 255) / 256, 256>>>(c1W1, DH,  O_11);
    prep_w_kernel<<<(DH  * 256 + 255) / 256, 256>>>(c1W2, DH,  O_12);
    prep_w_kernel<<<(DH  * 256 + 255) / 256, 256>>>(c2W1, DH,  O_21);
    prep_w_kernel<<<(DH  * 256 + 255) / 256, 256>>>(c2W2, DH,  O_22);

    // projections (tensor cores via mma.sync)
    tgemm_kernel<0><<<gridN, 256>>>(x,  pwh + O_WN, pwl + O_WN, bn, ph, nullptr, NN, DIN);
    tgemm_kernel<0><<<gridE, 256>>>(ea, pwh + O_WE, pwl + O_WE, be, pe, nullptr, NE, DIN);

    // two GINE layers
    for (int layer = 0; layer < 2; layer++) {
        const float* b1 = layer ? c2b1 : c1b1;
        const float* b2 = layer ? c2b2 : c1b2;
        const float* ep = layer ? eps2 : eps1;
        const int o1 = layer ? O_21 : O_11;
        const int o2 = layer ? O_22 : O_12;

        init_z_kernel<<<zblocks, 256>>>(ph, ep, pa);
        message_kernel<<<(NE * 32 + 255) / 256, 256>>>(ph, pe, pa);
        tgemm_kernel<1><<<gridN, 256>>>(pa, pwh + o1, pwl + o1, b1, pt, nullptr, NN, DH);
        tgemm_kernel<2><<<gridN, 256>>>(pt, pwh + o2, pwl + o2, b2, ph, ph, NN, DH);
    }

    // pooling + head
    zero_kernel<<<(NG * DH + 255) / 256, 256>>>(ppool, NG * DH);
    zero_kernel<<<1, 64>>>(pcnt, NG);
    pool_kernel<<<(NN + 99) / 100, 256>>>(ph, ppool, pcnt);
    root_kernel<<<(NN + 255) / 256, 256>>>(proot);
    final_kernel<<<NG, 256>>>(ph, ppool, pcnt, proot, Wo, bo, alpha, out);
}